// round 10
// baseline (speedup 1.0000x reference)
#include <cuda_runtime.h>
#include <cuda_bf16.h>

#define EPB 32                 // elements per block
#define BLK (EPB * 3)          // 3 warps: warp w handles matrix w
#define NSWEEP 4
#define SKIP_TOL2 1e-14f       // warp-uniform skip when all lanes |a|^2 < tol

// upper-triangle index, j<k, matches Gell-Mann sym/antisym ordering
__device__ __forceinline__ int uidx(int j, int k) {
    return j * 8 - (j * (j + 1)) / 2 + (k - j - 1);
}

__device__ __forceinline__ float rcp_approx(float x) {
    float r; asm("rcp.approx.f32 %0, %1;" : "=f"(r) : "f"(x)); return r;
}

__global__ __launch_bounds__(BLK)
void bes_kernel(const float* __restrict__ rho,
                const int* __restrict__ rank0p,
                const int* __restrict__ rank1p,
                float* __restrict__ out, int n)
{
    __shared__ float sv[EPB][65];    // staged input, padded rows
    __shared__ float ex[EPB][4];     // paMin, paMax, pcMin, pcMax exchange

    const int tid  = threadIdx.x;
    const int mat  = tid >> 5;       // warp id = matrix (0:H 1:PT_A 2:PT_C)
    const int e    = tid & 31;
    const int base = blockIdx.x * EPB;

    const int n0 = 8 - rank0p[0];
    const int n1 = 8 - rank1p[0];

    for (int i = tid; i < EPB * 63; i += BLK) {
        int t = i / 63;
        if (base + t < n) sv[t][i - t * 63] = rho[(long long)base * 63 + i];
    }
    __syncthreads();

    const float* v = sv[e];

    // --- normalize ---
    float ss = 0.f;
#pragma unroll
    for (int i = 0; i < 63; ++i) ss += v[i] * v[i];
    const float inv = rsqrtf(ss);

    // --- diagonal of H (traceless; I/8 folded out; PT preserves diagonal) ---
    const float CL1 = 1.0f, CL2 = 0.57735026919f, CL3 = 0.40824829046f,
                CL4 = 0.31622776601f, CL5 = 0.25819888975f,
                CL6 = 0.21821789023f, CL7 = 0.18898223650f;
    float f[8];
    f[0] = 0.f;
    f[1] = CL1 * v[56] * inv; f[2] = CL2 * v[57] * inv; f[3] = CL3 * v[58] * inv;
    f[4] = CL4 * v[59] * inv; f[5] = CL5 * v[60] * inv; f[6] = CL6 * v[61] * inv;
    f[7] = CL7 * v[62] * inv;
    float d8[8];
    {
        float suf = 0.f;
#pragma unroll
        for (int j = 7; j >= 0; --j) { d8[j] = suf - (float)j * f[j]; suf += f[j]; }
    }

    // --- build upper triangle: branchless PT permutation via bitmask select ---
    const int m  = (mat == 0) ? 7 : (mat == 1 ? 4 : 6);
    const int mc = 7 ^ m;
    float2 u[28];
#pragma unroll
    for (int j = 0; j < 8; ++j) {
#pragma unroll
        for (int k = j + 1; k < 8; ++k) {
            int r2 = (j & m) | (k & mc);
            int c2 = (k & m) | (j & mc);
            int rr = r2 < c2 ? r2 : c2;
            int cc = r2 < c2 ? c2 : r2;
            int m2 = uidx(rr, cc);
            float re = v[m2] * inv;
            float im = v[28 + m2] * inv;
            im = (r2 < c2) ? -im : im;
            u[uidx(j, k)] = make_float2(re, im);
        }
    }

    // --- fast-scaled cyclic complex Hermitian Jacobi ---
    // true A[j][k] = g_j g_k u~[j][k] off-diagonal (hs[k]=g_k^2, init 1);
    // diagonals d8 kept TRUE and exact (m +/- sv). J = T * diag(c,c), the
    // diag folded into hs:
    //   x~' = x~ + t_x y~,  y~' = y~ - t_y x~
    //   t_x = conj(a~) h_q/u0,  t_y = a~ h_p/u0,  u0 = delta + sv
    // Warp-uniform skip: if ALL lanes have true |a|^2 < SKIP_TOL2, the
    // rotation is identity to ~1e-7 in the eigenvalues (Weyl) -> skip.
    float hs[8];
#pragma unroll
    for (int i = 0; i < 8; ++i) hs[i] = 1.f;

#pragma unroll 1
    for (int sweep = 0; sweep < NSWEEP; ++sweep) {
#pragma unroll
        for (int p = 0; p < 8; ++p) {
#pragma unroll
            for (int q = p + 1; q < 8; ++q) {
                const int ipq = uidx(p, q);
                float2 apq = u[ipq];
                float hpq = hs[p] * hs[q];
                float b2 = (apq.x * apq.x + apq.y * apq.y) * hpq;   // true |a|^2
                if (__all_sync(0xffffffffu, b2 < SKIP_TOL2)) continue;
                float dp = d8[p], dq = d8[q];
                float delta = (dp - dq) * 0.5f;
                float mm    = (dp + dq) * 0.5f;
                float v2 = fmaf(delta, delta, b2);
                bool ok = v2 > 1e-30f;
                float rinv = rsqrtf(ok ? v2 : 1.f);
                float vv  = v2 * rinv;                  // sqrt(v2)
                float sv2 = copysignf(vv, delta);
                float u0  = delta + sv2;
                float c2  = fmaf(0.5f * fabsf(delta), rinv, 0.5f);
                c2 = ok ? c2 : 1.f;
                float rcpu = rcp_approx(u0);
                float sx = ok ? hs[q] * rcpu : 0.f;
                float sy = ok ? hs[p] * rcpu : 0.f;
                float txr =  apq.x * sx, txi = -apq.y * sx;  // t_x = conj(a~) h_q/u0
                float tyr =  apq.x * sy, tyi =  apq.y * sy;  // t_y = a~ h_p/u0
                d8[p] = mm + sv2;
                d8[q] = mm - sv2;
                hs[p] *= c2;
                hs[q] *= c2;
                u[ipq] = make_float2(0.f, 0.f);
#pragma unroll
                for (int k = 0; k < 8; ++k) {
                    if (k == p || k == q) continue;
                    float xr, xi, yr, yi;
                    if (k < p) { float2 tt = u[uidx(k, p)]; xr = tt.x; xi =  tt.y; }
                    else       { float2 tt = u[uidx(p, k)]; xr = tt.x; xi = -tt.y; }
                    if (k < q) { float2 tt = u[uidx(k, q)]; yr = tt.x; yi =  tt.y; }
                    else       { float2 tt = u[uidx(q, k)]; yr = tt.x; yi = -tt.y; }
                    float nxr = fmaf(txr, yr, fmaf(-txi, yi, xr));
                    float nxi = fmaf(txr, yi, fmaf( txi, yr, xi));
                    float nyr = fmaf(-tyr, xr, fmaf( tyi, xi, yr));
                    float nyi = fmaf(-tyr, xi, fmaf(-tyi, xr, yi));
                    if (k < p) u[uidx(k, p)] = make_float2(nxr,  nxi);
                    else       u[uidx(p, k)] = make_float2(nxr, -nxi);
                    if (k < q) u[uidx(k, q)] = make_float2(nyr,  nyi);
                    else       u[uidx(q, k)] = make_float2(nyr, -nyi);
                }
            }
        }
    }

    // --- reduce (warp-uniform branch on mat); d8 are true eigenvalues ---
    float l0 = 0.f, l7 = 0.f, sumS0 = 0.f, sumL0 = 0.f, sumS1 = 0.f, sumL1 = 0.f;
    if (mat == 0) {
#pragma unroll
        for (int i = 0; i < 7; ++i)
#pragma unroll
            for (int j = 0; j < 7 - i; ++j) {
                float lo = fminf(d8[j], d8[j + 1]);
                float hi = fmaxf(d8[j], d8[j + 1]);
                d8[j] = lo; d8[j + 1] = hi;
            }
        l0 = d8[0]; l7 = d8[7];
#pragma unroll
        for (int i = 0; i < 8; ++i) {
            if (i < n0)      sumS0 += d8[i];
            if (i >= 8 - n0) sumL0 += d8[i];
            if (i < n1)      sumS1 += d8[i];
            if (i >= 8 - n1) sumL1 += d8[i];
        }
    } else {
        float mn = d8[0], mx = d8[0];
#pragma unroll
        for (int i = 1; i < 8; ++i) { mn = fminf(mn, d8[i]); mx = fmaxf(mx, d8[i]); }
        ex[e][(mat - 1) * 2 + 0] = mn;
        ex[e][(mat - 1) * 2 + 1] = mx;
    }
    __syncthreads();

    if (mat == 0 && base + e < n) {
        float paMin = ex[e][0], paMax = ex[e][1];
        float pcMin = ex[e][2], pcMax = ex[e][3];

        const float beta0 = 1.f / (1.f - 8.f * (l0 + 0.125f));
        const float beta1 = 1.f / (1.f - 8.f * (l7 + 0.125f));

        float loss0 = beta0 * (beta0 >= 0.f ? sumS0 : sumL0) + (float)n0 * 0.125f;
        float loss1 = beta1 * (beta1 >= 0.f ? sumS1 : sumL1) + (float)n1 * 0.125f;
        float loss = (loss0 + loss1) * (loss0 + loss1);

        float lam;
        lam = beta0 * (beta0 >= 0.f ? paMin : paMax) + 0.125f; loss += lam * lam;
        lam = beta0 * (beta0 >= 0.f ? pcMin : pcMax) + 0.125f; loss += lam * lam;
        lam = beta1 * (beta1 >= 0.f ? paMin : paMax) + 0.125f; loss += lam * lam;
        lam = beta1 * (beta1 >= 0.f ? pcMin : pcMax) + 0.125f; loss += lam * lam;

        out[base + e] = loss;
    }
}

extern "C" void kernel_launch(void* const* d_in, const int* in_sizes, int n_in,
                              void* d_out, int out_size)
{
    const float* rho = (const float*)d_in[0];
    const int*   r0  = (const int*)d_in[1];
    const int*   r1  = (const int*)d_in[2];
    float* out = (float*)d_out;
    int n = in_sizes[0] / 63;
    int grid = (n + EPB - 1) / EPB;
    bes_kernel<<<grid, BLK>>>(rho, r0, r1, out, n);
}

// round 11
// speedup vs baseline: 1.1791x; 1.1791x over previous
#include <cuda_runtime.h>
#include <cuda_bf16.h>

#define EPB 32                 // elements per block
#define BLK (EPB * 3)          // 3 warps: warp w handles matrix w
#define NSWEEP 4

// upper-triangle index, j<k, matches Gell-Mann sym/antisym ordering
__device__ __forceinline__ int uidx(int j, int k) {
    return j * 8 - (j * (j + 1)) / 2 + (k - j - 1);
}

__device__ __forceinline__ float rcp_approx(float x) {
    float r; asm("rcp.approx.f32 %0, %1;" : "=f"(r) : "f"(x)); return r;
}

__global__ __launch_bounds__(BLK)
void bes_kernel(const float* __restrict__ rho,
                const int* __restrict__ rank0p,
                const int* __restrict__ rank1p,
                float* __restrict__ out, int n)
{
    // round-robin tournament order: consecutive pairs are DISJOINT, so each
    // rotation's rsqrt/rcp parameter chain is independent of the previous
    // rotation's update loop -> ptxas overlaps them (straight-line, no arrays).
    constexpr int PAIRS[28][2] = {
        {0,7},{1,6},{2,5},{3,4},
        {0,4},{1,7},{2,6},{3,5},
        {0,1},{2,7},{3,6},{4,5},
        {0,5},{1,2},{3,7},{4,6},
        {0,2},{1,3},{4,7},{5,6},
        {0,6},{1,4},{2,3},{5,7},
        {0,3},{1,5},{2,4},{6,7},
    };

    __shared__ float sv[EPB][65];    // staged input, padded rows
    __shared__ float ex[EPB][4];     // paMin, paMax, pcMin, pcMax exchange

    const int tid  = threadIdx.x;
    const int mat  = tid >> 5;       // warp id = matrix (0:H 1:PT_A 2:PT_C)
    const int e    = tid & 31;
    const int base = blockIdx.x * EPB;

    const int n0 = 8 - rank0p[0];
    const int n1 = 8 - rank1p[0];

    for (int i = tid; i < EPB * 63; i += BLK) {
        int t = i / 63;
        if (base + t < n) sv[t][i - t * 63] = rho[(long long)base * 63 + i];
    }
    __syncthreads();

    const float* v = sv[e];

    // --- normalize ---
    float ss = 0.f;
#pragma unroll
    for (int i = 0; i < 63; ++i) ss += v[i] * v[i];
    const float inv = rsqrtf(ss);

    // --- diagonal of H (traceless; I/8 folded out; PT preserves diagonal) ---
    const float CL1 = 1.0f, CL2 = 0.57735026919f, CL3 = 0.40824829046f,
                CL4 = 0.31622776601f, CL5 = 0.25819888975f,
                CL6 = 0.21821789023f, CL7 = 0.18898223650f;
    float f[8];
    f[0] = 0.f;
    f[1] = CL1 * v[56] * inv; f[2] = CL2 * v[57] * inv; f[3] = CL3 * v[58] * inv;
    f[4] = CL4 * v[59] * inv; f[5] = CL5 * v[60] * inv; f[6] = CL6 * v[61] * inv;
    f[7] = CL7 * v[62] * inv;
    float d8[8];
    {
        float suf = 0.f;
#pragma unroll
        for (int j = 7; j >= 0; --j) { d8[j] = suf - (float)j * f[j]; suf += f[j]; }
    }

    // --- build upper triangle: branchless PT permutation via bitmask select ---
    const int m  = (mat == 0) ? 7 : (mat == 1 ? 4 : 6);
    const int mc = 7 ^ m;
    float2 u[28];
#pragma unroll
    for (int j = 0; j < 8; ++j) {
#pragma unroll
        for (int k = j + 1; k < 8; ++k) {
            int r2 = (j & m) | (k & mc);
            int c2 = (k & m) | (j & mc);
            int rr = r2 < c2 ? r2 : c2;
            int cc = r2 < c2 ? c2 : r2;
            int m2 = uidx(rr, cc);
            float re = v[m2] * inv;
            float im = v[28 + m2] * inv;
            im = (r2 < c2) ? -im : im;
            u[uidx(j, k)] = make_float2(re, im);
        }
    }

    // --- fast-scaled Hermitian Jacobi, tournament order ---
    // true A[j][k] = g_j g_k u~[j][k] off-diagonal (hs[k]=g_k^2, init 1);
    // diagonals d8 kept TRUE and exact (m +/- sv). J = T*diag(c,c), the diag
    // folded into hs:
    //   x~' = x~ + t_x y~,  y~' = y~ - t_y x~
    //   t_x = conj(a~) h_q/u0,  t_y = a~ h_p/u0,  u0 = delta + sv
    //   c^2 = 0.5 + 0.5 |delta| rinv (reuses rinv = rsqrt(v2))
    float hs[8];
#pragma unroll
    for (int i = 0; i < 8; ++i) hs[i] = 1.f;

#pragma unroll 1
    for (int sweep = 0; sweep < NSWEEP; ++sweep) {
#pragma unroll
        for (int r = 0; r < 28; ++r) {
            const int p = PAIRS[r][0], q = PAIRS[r][1];
            const int ipq = uidx(p, q);
            float2 apq = u[ipq];
            float hpq = hs[p] * hs[q];
            float b2 = (apq.x * apq.x + apq.y * apq.y) * hpq;   // true |a|^2
            float dp = d8[p], dq = d8[q];
            float delta = (dp - dq) * 0.5f;
            float mm    = (dp + dq) * 0.5f;
            float v2 = fmaf(delta, delta, b2);
            bool ok = v2 > 1e-30f;
            float rinv = rsqrtf(ok ? v2 : 1.f);
            float vv  = v2 * rinv;                  // sqrt(v2)
            float sv2 = copysignf(vv, delta);
            float u0  = delta + sv2;
            float c2  = fmaf(0.5f * fabsf(delta), rinv, 0.5f);
            c2 = ok ? c2 : 1.f;
            float rcpu = rcp_approx(u0);
            float sx = ok ? hs[q] * rcpu : 0.f;
            float sy = ok ? hs[p] * rcpu : 0.f;
            float txr =  apq.x * sx, txi = -apq.y * sx;  // t_x = conj(a~) h_q/u0
            float tyr =  apq.x * sy, tyi =  apq.y * sy;  // t_y = a~ h_p/u0
            d8[p] = mm + sv2;
            d8[q] = mm - sv2;
            hs[p] *= c2;
            hs[q] *= c2;
            u[ipq] = make_float2(0.f, 0.f);
#pragma unroll
            for (int k = 0; k < 8; ++k) {
                if (k == p || k == q) continue;
                float xr, xi, yr, yi;
                if (k < p) { float2 tt = u[uidx(k, p)]; xr = tt.x; xi =  tt.y; }
                else       { float2 tt = u[uidx(p, k)]; xr = tt.x; xi = -tt.y; }
                if (k < q) { float2 tt = u[uidx(k, q)]; yr = tt.x; yi =  tt.y; }
                else       { float2 tt = u[uidx(q, k)]; yr = tt.x; yi = -tt.y; }
                float nxr = fmaf(txr, yr, fmaf(-txi, yi, xr));
                float nxi = fmaf(txr, yi, fmaf( txi, yr, xi));
                float nyr = fmaf(-tyr, xr, fmaf( tyi, xi, yr));
                float nyi = fmaf(-tyr, xi, fmaf(-tyi, xr, yi));
                if (k < p) u[uidx(k, p)] = make_float2(nxr,  nxi);
                else       u[uidx(p, k)] = make_float2(nxr, -nxi);
                if (k < q) u[uidx(k, q)] = make_float2(nyr,  nyi);
                else       u[uidx(q, k)] = make_float2(nyr, -nyi);
            }
        }
    }

    // --- reduce (warp-uniform branch on mat); d8 are true eigenvalues ---
    float l0 = 0.f, l7 = 0.f, sumS0 = 0.f, sumL0 = 0.f, sumS1 = 0.f, sumL1 = 0.f;
    if (mat == 0) {
#pragma unroll
        for (int i = 0; i < 7; ++i)
#pragma unroll
            for (int j = 0; j < 7 - i; ++j) {
                float lo = fminf(d8[j], d8[j + 1]);
                float hi = fmaxf(d8[j], d8[j + 1]);
                d8[j] = lo; d8[j + 1] = hi;
            }
        l0 = d8[0]; l7 = d8[7];
#pragma unroll
        for (int i = 0; i < 8; ++i) {
            if (i < n0)      sumS0 += d8[i];
            if (i >= 8 - n0) sumL0 += d8[i];
            if (i < n1)      sumS1 += d8[i];
            if (i >= 8 - n1) sumL1 += d8[i];
        }
    } else {
        float mn = d8[0], mx = d8[0];
#pragma unroll
        for (int i = 1; i < 8; ++i) { mn = fminf(mn, d8[i]); mx = fmaxf(mx, d8[i]); }
        ex[e][(mat - 1) * 2 + 0] = mn;
        ex[e][(mat - 1) * 2 + 1] = mx;
    }
    __syncthreads();

    if (mat == 0 && base + e < n) {
        float paMin = ex[e][0], paMax = ex[e][1];
        float pcMin = ex[e][2], pcMax = ex[e][3];

        const float beta0 = 1.f / (1.f - 8.f * (l0 + 0.125f));
        const float beta1 = 1.f / (1.f - 8.f * (l7 + 0.125f));

        float loss0 = beta0 * (beta0 >= 0.f ? sumS0 : sumL0) + (float)n0 * 0.125f;
        float loss1 = beta1 * (beta1 >= 0.f ? sumS1 : sumL1) + (float)n1 * 0.125f;
        float loss = (loss0 + loss1) * (loss0 + loss1);

        float lam;
        lam = beta0 * (beta0 >= 0.f ? paMin : paMax) + 0.125f; loss += lam * lam;
        lam = beta0 * (beta0 >= 0.f ? pcMin : pcMax) + 0.125f; loss += lam * lam;
        lam = beta1 * (beta1 >= 0.f ? paMin : paMax) + 0.125f; loss += lam * lam;
        lam = beta1 * (beta1 >= 0.f ? pcMin : pcMax) + 0.125f; loss += lam * lam;

        out[base + e] = loss;
    }
}

extern "C" void kernel_launch(void* const* d_in, const int* in_sizes, int n_in,
                              void* d_out, int out_size)
{
    const float* rho = (const float*)d_in[0];
    const int*   r0  = (const int*)d_in[1];
    const int*   r1  = (const int*)d_in[2];
    float* out = (float*)d_out;
    int n = in_sizes[0] / 63;
    int grid = (n + EPB - 1) / EPB;
    bes_kernel<<<grid, BLK>>>(rho, r0, r1, out, n);
}